// round 12
// baseline (speedup 1.0000x reference)
#include <cuda_runtime.h>
#include <math.h>
#include <stdint.h>

#define D 128
#define NRELS 16
#define MAXN 50000
#define MAXE 800000
#define MAXNT 400
#define NBMAX (NRELS * MAXNT)

// ---------------- scratch (__device__ globals) ------------------------------
__device__ float g_hall[(size_t)NRELS * MAXN * D];   // [r][n][d]
__device__ float g_glog[(size_t)MAXN * NRELS];       // [n][r] (pk = s*16+r)
__device__ float g_h1[(size_t)MAXN * D];             // layer-0 out (fp32)
__device__ float g_atf[(size_t)MAXN * D];            // layer input tf32-rounded
__device__ float g_wt0[(size_t)NRELS * D * D];       // W0^T tf32
__device__ float g_wt1[(size_t)NRELS * D * D];       // W1^T tf32
__device__ float g_lwt0[(size_t)D * D];
__device__ float g_lwt1[(size_t)D * D];
__device__ int   g_cnt[NBMAX];
__device__ int   g_cur[NBMAX];
__device__ int   g_rp[NBMAX + 1];
__device__ int   g_spk[MAXE];                        // sorted src*16+rel
__device__ int   g_sdst[MAXE];                       // sorted dst
__device__ float g_snorm[MAXE];                      // sorted norm

__device__ __forceinline__ float f2tf32f(float x) {
    uint32_t y;
    asm("cvt.rna.tf32.f32 %0, %1;" : "=r"(y) : "f"(x));
    return __uint_as_float(y);
}
__device__ __forceinline__ uint32_t smem_u32(const void* p) {
    uint32_t a;
    asm("{ .reg .u64 t; cvta.to.shared.u64 t, %1; cvt.u32.u64 %0, t; }"
        : "=r"(a) : "l"(p));
    return a;
}
__device__ __forceinline__ void cp16(uint32_t dst, const void* src, int srcBytes) {
    asm volatile("cp.async.cg.shared.global [%0], [%1], 16, %2;"
                 :: "r"(dst), "l"(src), "r"(srcBytes) : "memory");
}
#define CP_COMMIT() asm volatile("cp.async.commit_group;" ::: "memory")
#define CP_WAIT0()  asm volatile("cp.async.wait_group 0;" ::: "memory")

// ---------------------------------------------------------------------------
// R4-proven relation-looped tf32 GEMM: BM=128, 256 threads, 8 warps (2m x 4n),
// warp tile 64x32. A resident full-K; B[r] double-buffered full tiles.
// Computes C[rBase+r] = A @ B[rBase+r] for r in [0, Rper).
// ---------------------------------------------------------------------------
#define SROW 132
#define TILE_B (128 * SROW * 4)          // 67584
#define GEMM_SMEM (3 * TILE_B + 128)     // 202880

__global__ __launch_bounds__(256)
void gemm_rloop(const float* __restrict__ A, const float* __restrict__ B,
                float* __restrict__ C0, size_t strideC, int rBase, int Rper,
                int M, const float* __restrict__ bias)
{
    extern __shared__ char smem[];
    const uint32_t sA  = smem_u32(smem);
    const uint32_t sB0 = sA + TILE_B;
    const uint32_t sB1 = sB0 + TILE_B;

    const int tid  = threadIdx.x;
    const int lane = tid & 31;
    const int wid  = tid >> 5;
    const int warp_m = wid & 1;
    const int warp_n = wid >> 1;
    const int g = lane >> 2;
    const int c = lane & 3;
    const int mBase = blockIdx.x * 128;

#pragma unroll
    for (int it = 0; it < 16; it++) {
        int i = tid + it * 256;
        int row = i >> 5;
        int c4  = (i & 31) * 4;
        bool valid = (mBase + row) < M;
        const float* src = A + (valid ? ((size_t)(mBase + row) * D + c4) : 0);
        cp16(sA + (uint32_t)(row * SROW + c4) * 4, src, valid ? 16 : 0);
    }
    {
        const float* B0 = B + (size_t)rBase * D * D;
#pragma unroll
        for (int it = 0; it < 16; it++) {
            int i = tid + it * 256;
            int row = i >> 5;
            int c4  = (i & 31) * 4;
            cp16(sB0 + (uint32_t)(row * SROW + c4) * 4,
                 B0 + (size_t)row * D + c4, 16);
        }
    }
    CP_COMMIT();
    CP_WAIT0();
    __syncthreads();

    const uint32_t aBase = sA + (uint32_t)(warp_m * 64) * SROW * 4;

    for (int r = 0; r < Rper; r++) {
        const uint32_t sCur = (r & 1) ? sB1 : sB0;
        const uint32_t sNxt = (r & 1) ? sB0 : sB1;

        if (r + 1 < Rper) {
            const float* Bn = B + (size_t)(rBase + r + 1) * D * D;
#pragma unroll
            for (int it = 0; it < 16; it++) {
                int i = tid + it * 256;
                int row = i >> 5;
                int c4  = (i & 31) * 4;
                cp16(sNxt + (uint32_t)(row * SROW + c4) * 4,
                     Bn + (size_t)row * D + c4, 16);
            }
            CP_COMMIT();
        }

        float acc[4][4][4];
#pragma unroll
        for (int mi = 0; mi < 4; mi++)
#pragma unroll
            for (int ni = 0; ni < 4; ni++)
#pragma unroll
                for (int f = 0; f < 4; f++) acc[mi][ni][f] = 0.f;

        const uint32_t bBase = sCur + (uint32_t)(warp_n * 32) * SROW * 4;

#pragma unroll
        for (int kc = 0; kc < 16; kc++) {
            const int kb = kc * 8;
            uint32_t af[4][4], bf[4][2];
#pragma unroll
            for (int mi = 0; mi < 4; mi++) {
                uint32_t a0 = aBase + (uint32_t)((mi * 16 + g) * SROW + kb + c) * 4;
                asm volatile("ld.shared.b32 %0, [%1];"    : "=r"(af[mi][0]) : "r"(a0));
                asm volatile("ld.shared.b32 %0, [%1+16];" : "=r"(af[mi][2]) : "r"(a0));
                uint32_t a1 = a0 + 8u * SROW * 4u;
                asm volatile("ld.shared.b32 %0, [%1];"    : "=r"(af[mi][1]) : "r"(a1));
                asm volatile("ld.shared.b32 %0, [%1+16];" : "=r"(af[mi][3]) : "r"(a1));
            }
#pragma unroll
            for (int ni = 0; ni < 4; ni++) {
                uint32_t b0 = bBase + (uint32_t)((ni * 8 + g) * SROW + kb + c) * 4;
                asm volatile("ld.shared.b32 %0, [%1];"    : "=r"(bf[ni][0]) : "r"(b0));
                asm volatile("ld.shared.b32 %0, [%1+16];" : "=r"(bf[ni][1]) : "r"(b0));
            }
#pragma unroll
            for (int mi = 0; mi < 4; mi++)
#pragma unroll
                for (int ni = 0; ni < 4; ni++) {
                    asm volatile(
                        "mma.sync.aligned.m16n8k8.row.col.f32.tf32.tf32.f32 "
                        "{%0,%1,%2,%3}, {%4,%5,%6,%7}, {%8,%9}, {%0,%1,%2,%3};\n"
                        : "+f"(acc[mi][ni][0]), "+f"(acc[mi][ni][1]),
                          "+f"(acc[mi][ni][2]), "+f"(acc[mi][ni][3])
                        : "r"(af[mi][0]), "r"(af[mi][1]),
                          "r"(af[mi][2]), "r"(af[mi][3]),
                          "r"(bf[ni][0]), "r"(bf[ni][1]));
                }
        }

        float* C = C0 + (size_t)(rBase + r) * strideC;
#pragma unroll
        for (int mi = 0; mi < 4; mi++) {
            const int row0 = mBase + warp_m * 64 + mi * 16 + g;
            const int row1 = row0 + 8;
#pragma unroll
            for (int ni = 0; ni < 4; ni++) {
                const int col = warp_n * 32 + ni * 8 + c * 2;
                float bx = 0.f, by = 0.f;
                if (bias != nullptr) { bx = bias[col]; by = bias[col + 1]; }
                if (row0 < M)
                    *(float2*)(C + (size_t)row0 * D + col) =
                        make_float2(acc[mi][ni][0] + bx, acc[mi][ni][1] + by);
                if (row1 < M)
                    *(float2*)(C + (size_t)row1 * D + col) =
                        make_float2(acc[mi][ni][2] + bx, acc[mi][ni][3] + by);
            }
        }

        if (r + 1 < Rper) {
            CP_WAIT0();
            __syncthreads();
        }
    }
}

// ---------------------------------------------------------------------------
// preprocessing: bucket edges by (rel, src>>7); pack sorted meta arrays
// ---------------------------------------------------------------------------
__global__ void hist_kernel(const int* __restrict__ src, const int* __restrict__ rel,
                            int E, int NT)
{
    int e = blockIdx.x * blockDim.x + threadIdx.x;
    if (e < E) atomicAdd(&g_cnt[rel[e] * NT + (src[e] >> 7)], 1);
}

__global__ void scan_kernel(int nb)
{
    __shared__ int part[1024];
    const int tid = threadIdx.x;
    const int per = (nb + 1023) / 1024;
    const int base = tid * per;
    int s = 0;
    for (int i = 0; i < per; i++)
        if (base + i < nb) s += g_cnt[base + i];
    part[tid] = s;
    __syncthreads();
    for (int off = 1; off < 1024; off <<= 1) {
        int v = (tid >= off) ? part[tid - off] : 0;
        __syncthreads();
        part[tid] += v;
        __syncthreads();
    }
    int run = (tid > 0) ? part[tid - 1] : 0;
    for (int i = 0; i < per; i++) {
        if (base + i < nb) {
            g_rp[base + i] = run;
            run += g_cnt[base + i];
        }
    }
    if (tid == 1023) g_rp[nb] = part[1023];
}

__global__ void fill_kernel(const int* __restrict__ src, const int* __restrict__ dst,
                            const int* __restrict__ rel, const float* __restrict__ norm,
                            int E, int NT)
{
    int e = blockIdx.x * blockDim.x + threadIdx.x;
    if (e >= E) return;
    int key = rel[e] * NT + (src[e] >> 7);
    int pos = g_rp[key] + atomicAdd(&g_cur[key], 1);
    g_spk[pos]   = src[e] * NRELS + rel[e];
    g_sdst[pos]  = dst[e];
    g_snorm[pos] = norm[e];
}

// ---------------------------------------------------------------------------
// Edge scatter over a bucket range [g_rp[loB], g_rp[hiB]) of the sorted edge
// list: EPW=4 edges per warp, red.global.add.v4. Sorted order gives hall-row
// locality (L1/L2 dedup of repeated (rel,src) rows).
// ---------------------------------------------------------------------------
#define EPW 4
__global__ void scatter_kernel(float* __restrict__ out, int loB, int hiB, int Nn)
{
    const int lo = g_rp[loB], hi = g_rp[hiB];
    int warp = (int)((blockIdx.x * blockDim.x + threadIdx.x) >> 5);
    int lane = threadIdx.x & 31;
    int base = lo + warp * EPW;
    if (base >= hi) return;

    float4 v[EPW];
    float gc[EPW];
    int dv[EPW];
    int cnt = min(EPW, hi - base);
#pragma unroll
    for (int i = 0; i < EPW; i++) {
        if (i >= cnt) break;
        int idx = base + i;
        int pk = __ldg(g_spk + idx);
        dv[i]  = __ldg(g_sdst + idx);
        float nm = __ldg(g_snorm + idx);
        float gl = g_glog[pk];
        gc[i] = nm / (1.f + expf(-gl));
        int s = pk >> 4;
        int r = pk & 15;
        v[i] = ((const float4*)(g_hall + ((size_t)r * Nn + s) * D))[lane];
    }
#pragma unroll
    for (int i = 0; i < EPW; i++) {
        if (i >= cnt) break;
        float* o = out + (size_t)dv[i] * D + lane * 4;
        asm volatile("red.global.add.v4.f32 [%0], {%1,%2,%3,%4};"
                     :: "l"(o), "f"(v[i].x * gc[i]), "f"(v[i].y * gc[i]),
                        "f"(v[i].z * gc[i]), "f"(v[i].w * gc[i])
                     : "memory");
    }
}

// ---------------------------------------------------------------------------
__global__ void round_kernel(const float* __restrict__ x, float* __restrict__ y,
                             size_t n)
{
    size_t i = (size_t)blockIdx.x * blockDim.x + threadIdx.x;
    if (i < n) y[i] = f2tf32f(x[i]);
}

__global__ void round_wT_kernel(const float* __restrict__ W,
                                float* __restrict__ out, int R)
{
    int i = blockIdx.x * blockDim.x + threadIdx.x;
    if (i >= R * D * D) return;
    int r = i / (D * D);
    int e = (i / D) & (D - 1);
    int d = i & (D - 1);
    out[i] = f2tf32f(W[(size_t)r * D * D + (size_t)d * D + e]);
}

__global__ void glog_kernel(const float* __restrict__ h, const float* __restrict__ gw,
                            int Nn)
{
    int warp = (int)((blockIdx.x * blockDim.x + threadIdx.x) >> 5);
    int lane = threadIdx.x & 31;
    if (warp >= Nn) return;
    float4 hv = ((const float4*)(h + (size_t)warp * D))[lane];
    float mine = 0.f;
#pragma unroll
    for (int r = 0; r < NRELS; r++) {
        float4 gv = ((const float4*)(gw + r * D))[lane];
        float dot = hv.x * gv.x + hv.y * gv.y + hv.z * gv.z + hv.w * gv.w;
#pragma unroll
        for (int off = 16; off > 0; off >>= 1)
            dot += __shfl_down_sync(0xffffffffu, dot, off);
        dot = __shfl_sync(0xffffffffu, dot, 0);
        if (lane == r) mine = dot;
    }
    if (lane < NRELS) g_glog[(size_t)warp * NRELS + lane] = mine;
}

// relu in place + tf32-rounded copy
__global__ void relu_round_kernel(float* __restrict__ x, float* __restrict__ y,
                                  size_t n)
{
    size_t i = (size_t)blockIdx.x * blockDim.x + threadIdx.x;
    if (i >= n) return;
    float v = fmaxf(x[i], 0.f);
    x[i] = v;
    y[i] = f2tf32f(v);
}

// ---------------------------------------------------------------------------
extern "C" void kernel_launch(void* const* d_in, const int* in_sizes, int n_in,
                              void* d_out, int out_size)
{
    const float* h    = (const float*)d_in[0];
    const float* norm = (const float*)d_in[1];
    const float* W0   = (const float*)d_in[2];
    const float* b0   = (const float*)d_in[3];
    const float* lw0  = (const float*)d_in[4];
    const float* gw0  = (const float*)d_in[5];
    const float* W1   = (const float*)d_in[6];
    const float* b1   = (const float*)d_in[7];
    const float* lw1  = (const float*)d_in[8];
    const float* gw1  = (const float*)d_in[9];
    const int*   src  = (const int*)d_in[10];
    const int*   dst  = (const int*)d_in[11];
    const int*   rel  = (const int*)d_in[12];
    float* out = (float*)d_out;

    int Nn = in_sizes[0] / D;
    int E  = in_sizes[10];
    int NT = (Nn + 127) / 128;
    size_t nElem = (size_t)Nn * D;
    int mtiles = NT;

    // persistent side stream + events (created once; host-side objects)
    static cudaStream_t s2 = nullptr;
    static cudaEvent_t ev[6];
    if (s2 == nullptr) {
        cudaStreamCreateWithFlags(&s2, cudaStreamNonBlocking);
        for (int i = 0; i < 6; i++)
            cudaEventCreateWithFlags(&ev[i], cudaEventDisableTiming);
        cudaFuncSetAttribute(gemm_rloop,
                             cudaFuncAttributeMaxDynamicSharedMemorySize, GEMM_SMEM);
    }

    float *hall_ptr, *h1_ptr, *atf, *wt0, *wt1, *lwt0, *lwt1;
    int *cnt, *cur;
    cudaGetSymbolAddress((void**)&hall_ptr, g_hall);
    cudaGetSymbolAddress((void**)&h1_ptr, g_h1);
    cudaGetSymbolAddress((void**)&atf, g_atf);
    cudaGetSymbolAddress((void**)&wt0, g_wt0);
    cudaGetSymbolAddress((void**)&wt1, g_wt1);
    cudaGetSymbolAddress((void**)&lwt0, g_lwt0);
    cudaGetSymbolAddress((void**)&lwt1, g_lwt1);
    cudaGetSymbolAddress((void**)&cnt, g_cnt);
    cudaGetSymbolAddress((void**)&cur, g_cur);

    const int scatterBlocks = ((E + EPW - 1) / EPW * 32 + 255) / 256;
    const int splitB = (NRELS / 2) * NT;     // bucket index at rel==8

    // ---- preprocess (shared by both layers) + upfront weight rounding ------
    cudaMemsetAsync(cnt, 0, NBMAX * sizeof(int), 0);
    cudaMemsetAsync(cur, 0, NBMAX * sizeof(int), 0);
    hist_kernel<<<(E + 255) / 256, 256, 0, 0>>>(src, rel, E, NT);
    scan_kernel<<<1, 1024, 0, 0>>>(NRELS * NT);
    fill_kernel<<<(E + 255) / 256, 256, 0, 0>>>(src, dst, rel, norm, E, NT);
    round_wT_kernel<<<(NRELS * D * D + 255) / 256, 256, 0, 0>>>(W0, wt0, NRELS);
    round_wT_kernel<<<(NRELS * D * D + 255) / 256, 256, 0, 0>>>(W1, wt1, NRELS);
    round_wT_kernel<<<(D * D + 255) / 256, 256, 0, 0>>>(lw0, lwt0, 1);
    round_wT_kernel<<<(D * D + 255) / 256, 256, 0, 0>>>(lw1, lwt1, 1);
    round_kernel<<<(int)((nElem + 255) / 256), 256, 0, 0>>>(h, atf, nElem);

    // ================= Layer 0 ==============================================
    glog_kernel<<<(Nn * 32 + 255) / 256, 256, 0, 0>>>(h, gw0, Nn);
    // h1 = h @ loop_w0 + b0 (accumulation target)
    gemm_rloop<<<mtiles, 256, GEMM_SMEM, 0>>>(atf, lwt0, h1_ptr, 0, 0, 1, Nn, b0);
    // hall rels 0-7, then 8-15
    gemm_rloop<<<mtiles, 256, GEMM_SMEM, 0>>>(atf, wt0, hall_ptr, (size_t)Nn * D,
                                              0, NRELS / 2, Nn, nullptr);
    cudaEventRecord(ev[0], 0);
    gemm_rloop<<<mtiles, 256, GEMM_SMEM, 0>>>(atf, wt0, hall_ptr, (size_t)Nn * D,
                                              NRELS / 2, NRELS / 2, Nn, nullptr);
    cudaEventRecord(ev[1], 0);
    // scatters on side stream, overlapping gemm half 2
    cudaStreamWaitEvent(s2, ev[0], 0);
    scatter_kernel<<<scatterBlocks, 256, 0, s2>>>(h1_ptr, 0, splitB, Nn);
    cudaStreamWaitEvent(s2, ev[1], 0);
    scatter_kernel<<<scatterBlocks, 256, 0, s2>>>(h1_ptr, splitB, NRELS * NT, Nn);
    cudaEventRecord(ev[2], s2);
    cudaStreamWaitEvent(0, ev[2], 0);
    // relu + tf32 copy for layer 1
    relu_round_kernel<<<(int)((nElem + 255) / 256), 256, 0, 0>>>(h1_ptr, atf, nElem);

    // ================= Layer 1 ==============================================
    glog_kernel<<<(Nn * 32 + 255) / 256, 256, 0, 0>>>(h1_ptr, gw1, Nn);
    gemm_rloop<<<mtiles, 256, GEMM_SMEM, 0>>>(atf, lwt1, out, 0, 0, 1, Nn, b1);
    gemm_rloop<<<mtiles, 256, GEMM_SMEM, 0>>>(atf, wt1, hall_ptr, (size_t)Nn * D,
                                              0, NRELS / 2, Nn, nullptr);
    cudaEventRecord(ev[3], 0);
    gemm_rloop<<<mtiles, 256, GEMM_SMEM, 0>>>(atf, wt1, hall_ptr, (size_t)Nn * D,
                                              NRELS / 2, NRELS / 2, Nn, nullptr);
    cudaEventRecord(ev[4], 0);
    cudaStreamWaitEvent(s2, ev[3], 0);
    scatter_kernel<<<scatterBlocks, 256, 0, s2>>>(out, 0, splitB, Nn);
    cudaStreamWaitEvent(s2, ev[4], 0);
    scatter_kernel<<<scatterBlocks, 256, 0, s2>>>(out, splitB, NRELS * NT, Nn);
    cudaEventRecord(ev[5], s2);
    cudaStreamWaitEvent(0, ev[5], 0);
}

// round 13
// speedup vs baseline: 1.1234x; 1.1234x over previous
#include <cuda_runtime.h>
#include <cuda_fp16.h>
#include <math.h>
#include <stdint.h>

#define D 128
#define NRELS 16
#define MAXN 50000
#define MAXE 800000
#define MAXNT 400
#define NBMAX (NRELS * MAXNT)

// ---------------- scratch (__device__ globals) ------------------------------
__device__ __half g_hallh[(size_t)NRELS * MAXN * D]; // [r][n][d] fp16 messages
__device__ float g_gate[(size_t)MAXN * NRELS];       // sigmoid(glog), pk=s*16+r
__device__ float g_h1[(size_t)MAXN * D];             // layer-0 out (fp32)
__device__ float g_atf[(size_t)MAXN * D];            // layer input tf32-rounded
__device__ float g_wt0[(size_t)NRELS * D * D];
__device__ float g_wt1[(size_t)NRELS * D * D];
__device__ float g_lwt0[(size_t)D * D];
__device__ float g_lwt1[(size_t)D * D];
__device__ int   g_cnt[NBMAX];
__device__ int   g_cur[NBMAX];
__device__ int   g_rp[NBMAX + 1];
__device__ int   g_spk[MAXE];                        // sorted src*16+rel
__device__ int   g_sdst[MAXE];                       // sorted dst
__device__ float g_snorm[MAXE];                      // sorted norm

__device__ __forceinline__ float f2tf32f(float x) {
    uint32_t y;
    asm("cvt.rna.tf32.f32 %0, %1;" : "=r"(y) : "f"(x));
    return __uint_as_float(y);
}
__device__ __forceinline__ uint32_t smem_u32(const void* p) {
    uint32_t a;
    asm("{ .reg .u64 t; cvta.to.shared.u64 t, %1; cvt.u32.u64 %0, t; }"
        : "=r"(a) : "l"(p));
    return a;
}
__device__ __forceinline__ void cp16(uint32_t dst, const void* src, int srcBytes) {
    asm volatile("cp.async.cg.shared.global [%0], [%1], 16, %2;"
                 :: "r"(dst), "l"(src), "r"(srcBytes) : "memory");
}
#define CP_COMMIT() asm volatile("cp.async.commit_group;" ::: "memory")
#define CP_WAIT0()  asm volatile("cp.async.wait_group 0;" ::: "memory")

#define SROW_A 132
#define SROW_B 68
#define SM_A_BYTES (256 * SROW_A * 4)
#define SM_BCHUNK  (128 * SROW_B * 4)
#define GEMM_SMEM  (SM_A_BYTES + 2 * SM_BCHUNK)   // 204800

// ---------------------------------------------------------------------------
// R5-proven tf32 GEMM: 512 threads, BM=256, BN=128, warp tile 64x32
// (16 warps: 4m x 4n). Relation-looped, B double-buffered in half-K chunks.
// HALF_OUT=1: C is fp16 (hall messages). HALF_OUT=0: C fp32 (+bias).
// ---------------------------------------------------------------------------
template <int HALF_OUT>
__global__ __launch_bounds__(512)
void gemm_v2(const float* __restrict__ A, const float* __restrict__ B,
             void* __restrict__ C0v, size_t strideC, int Rper, int M,
             const float* __restrict__ bias)
{
    extern __shared__ char smem[];
    const uint32_t sA  = smem_u32(smem);
    const uint32_t sB0 = sA + SM_A_BYTES;
    const uint32_t sB1 = sB0 + SM_BCHUNK;

    const int tid  = threadIdx.x;
    const int lane = tid & 31;
    const int wid  = tid >> 5;
    const int warp_m = wid >> 2;
    const int warp_n = wid & 3;
    const int g = lane >> 2;
    const int c = lane & 3;
    const int mBase = blockIdx.x * 256;
    const int rBase = blockIdx.y * Rper;
    const int nChunks = 2 * Rper;

#pragma unroll
    for (int it = 0; it < 16; it++) {
        int i = tid + it * 512;
        int row = i >> 5;
        int c4  = (i & 31) * 4;
        bool valid = (mBase + row) < M;
        const float* src = A + (valid ? ((size_t)(mBase + row) * D + c4) : 0);
        cp16(sA + (uint32_t)(row * SROW_A + c4) * 4, src, valid ? 16 : 0);
    }
    {
        const float* Bc = B + (size_t)rBase * D * D;
#pragma unroll
        for (int it = 0; it < 4; it++) {
            int i = tid + it * 512;
            int row = i >> 4;
            int c4  = (i & 15) * 4;
            cp16(sB0 + (uint32_t)(row * SROW_B + c4) * 4,
                 Bc + (size_t)row * D + c4, 16);
        }
    }
    CP_COMMIT();
    CP_WAIT0();
    __syncthreads();

    const uint32_t aBase = sA + (uint32_t)(warp_m * 64) * SROW_A * 4;
    float acc[4][4][4];

    for (int j = 0; j < nChunks; j++) {
        const uint32_t sCur = (j & 1) ? sB1 : sB0;

        if (j + 1 < nChunks) {
            const uint32_t sNxt = (j & 1) ? sB0 : sB1;
            const int r1 = rBase + ((j + 1) >> 1);
            const int h1 = ((j + 1) & 1) * 64;
            const float* Bc = B + (size_t)r1 * D * D + h1;
#pragma unroll
            for (int it = 0; it < 4; it++) {
                int i = tid + it * 512;
                int row = i >> 4;
                int c4  = (i & 15) * 4;
                cp16(sNxt + (uint32_t)(row * SROW_B + c4) * 4,
                     Bc + (size_t)row * D + c4, 16);
            }
            CP_COMMIT();
        }

        if (!(j & 1)) {
#pragma unroll
            for (int mi = 0; mi < 4; mi++)
#pragma unroll
                for (int ni = 0; ni < 4; ni++)
#pragma unroll
                    for (int f = 0; f < 4; f++) acc[mi][ni][f] = 0.f;
        }

        const int kbGlob = (j & 1) * 64;
        const uint32_t bBase = sCur + (uint32_t)(warp_n * 32) * SROW_B * 4;
#pragma unroll
        for (int kc = 0; kc < 8; kc++) {
            const int kbA = kbGlob + kc * 8;
            const int kbB = kc * 8;
            uint32_t af[4][4], bf[4][2];
#pragma unroll
            for (int mi = 0; mi < 4; mi++) {
                uint32_t a0 = aBase + (uint32_t)((mi * 16 + g) * SROW_A + kbA + c) * 4;
                asm volatile("ld.shared.b32 %0, [%1];"    : "=r"(af[mi][0]) : "r"(a0));
                asm volatile("ld.shared.b32 %0, [%1+16];" : "=r"(af[mi][2]) : "r"(a0));
                uint32_t a1 = a0 + 8u * SROW_A * 4u;
                asm volatile("ld.shared.b32 %0, [%1];"    : "=r"(af[mi][1]) : "r"(a1));
                asm volatile("ld.shared.b32 %0, [%1+16];" : "=r"(af[mi][3]) : "r"(a1));
            }
#pragma unroll
            for (int ni = 0; ni < 4; ni++) {
                uint32_t b0 = bBase + (uint32_t)((ni * 8 + g) * SROW_B + kbB + c) * 4;
                asm volatile("ld.shared.b32 %0, [%1];"    : "=r"(bf[ni][0]) : "r"(b0));
                asm volatile("ld.shared.b32 %0, [%1+16];" : "=r"(bf[ni][1]) : "r"(b0));
            }
#pragma unroll
            for (int mi = 0; mi < 4; mi++)
#pragma unroll
                for (int ni = 0; ni < 4; ni++) {
                    asm volatile(
                        "mma.sync.aligned.m16n8k8.row.col.f32.tf32.tf32.f32 "
                        "{%0,%1,%2,%3}, {%4,%5,%6,%7}, {%8,%9}, {%0,%1,%2,%3};\n"
                        : "+f"(acc[mi][ni][0]), "+f"(acc[mi][ni][1]),
                          "+f"(acc[mi][ni][2]), "+f"(acc[mi][ni][3])
                        : "r"(af[mi][0]), "r"(af[mi][1]),
                          "r"(af[mi][2]), "r"(af[mi][3]),
                          "r"(bf[ni][0]), "r"(bf[ni][1]));
                }
        }

        if (j & 1) {
            const int r = rBase + (j >> 1);
#pragma unroll
            for (int mi = 0; mi < 4; mi++) {
                const int row0 = mBase + warp_m * 64 + mi * 16 + g;
                const int row1 = row0 + 8;
#pragma unroll
                for (int ni = 0; ni < 4; ni++) {
                    const int col = warp_n * 32 + ni * 8 + c * 2;
                    if (HALF_OUT) {
                        __half* C = (__half*)C0v + (size_t)r * strideC;
                        if (row0 < M)
                            *(__half2*)(C + (size_t)row0 * D + col) =
                                __floats2half2_rn(acc[mi][ni][0], acc[mi][ni][1]);
                        if (row1 < M)
                            *(__half2*)(C + (size_t)row1 * D + col) =
                                __floats2half2_rn(acc[mi][ni][2], acc[mi][ni][3]);
                    } else {
                        float* C = (float*)C0v + (size_t)r * strideC;
                        float bx = 0.f, by = 0.f;
                        if (bias != nullptr) { bx = bias[col]; by = bias[col + 1]; }
                        if (row0 < M)
                            *(float2*)(C + (size_t)row0 * D + col) =
                                make_float2(acc[mi][ni][0] + bx, acc[mi][ni][1] + by);
                        if (row1 < M)
                            *(float2*)(C + (size_t)row1 * D + col) =
                                make_float2(acc[mi][ni][2] + bx, acc[mi][ni][3] + by);
                    }
                }
            }
        }

        if (j + 1 < nChunks) {
            CP_WAIT0();
            __syncthreads();
        }
    }
}

// ---------------------------------------------------------------------------
// preprocessing: bucket edges by (rel, src>>7); pack sorted meta arrays
// ---------------------------------------------------------------------------
__global__ void hist_kernel(const int* __restrict__ src, const int* __restrict__ rel,
                            int E, int NT)
{
    int e = blockIdx.x * blockDim.x + threadIdx.x;
    if (e < E) atomicAdd(&g_cnt[rel[e] * NT + (src[e] >> 7)], 1);
}

__global__ void scan_kernel(int nb)
{
    __shared__ int part[1024];
    const int tid = threadIdx.x;
    const int per = (nb + 1023) / 1024;
    const int base = tid * per;
    int s = 0;
    for (int i = 0; i < per; i++)
        if (base + i < nb) s += g_cnt[base + i];
    part[tid] = s;
    __syncthreads();
    for (int off = 1; off < 1024; off <<= 1) {
        int v = (tid >= off) ? part[tid - off] : 0;
        __syncthreads();
        part[tid] += v;
        __syncthreads();
    }
    int run = (tid > 0) ? part[tid - 1] : 0;
    for (int i = 0; i < per; i++) {
        if (base + i < nb) {
            g_rp[base + i] = run;
            run += g_cnt[base + i];
        }
    }
    if (tid == 1023) g_rp[nb] = part[1023];
}

__global__ void fill_kernel(const int* __restrict__ src, const int* __restrict__ dst,
                            const int* __restrict__ rel, const float* __restrict__ norm,
                            int E, int NT)
{
    int e = blockIdx.x * blockDim.x + threadIdx.x;
    if (e >= E) return;
    int key = rel[e] * NT + (src[e] >> 7);
    int pos = g_rp[key] + atomicAdd(&g_cur[key], 1);
    g_spk[pos]   = src[e] * NRELS + rel[e];
    g_sdst[pos]  = dst[e];
    g_snorm[pos] = norm[e];
}

// ---------------------------------------------------------------------------
// Edge scatter over sorted edge list: EPW=4 edges/warp, fp16 hall reads
// (8 B/lane), fp32 red.global.add.v4. Sorted order -> L1-resident row window.
// ---------------------------------------------------------------------------
#define EPW 4
__global__ void scatter_kernel(float* __restrict__ out, int E, int Nn)
{
    int warp = (int)((blockIdx.x * blockDim.x + threadIdx.x) >> 5);
    int lane = threadIdx.x & 31;
    int base = warp * EPW;
    if (base >= E) return;

    float4 v[EPW];
    int dv[EPW];
    int cnt = min(EPW, E - base);
#pragma unroll
    for (int i = 0; i < EPW; i++) {
        if (i >= cnt) break;
        int idx = base + i;
        int pk = __ldg(g_spk + idx);
        dv[i]  = __ldg(g_sdst + idx);
        float nm = __ldg(g_snorm + idx);
        float gc = nm * __ldg(g_gate + pk);
        int s = pk >> 4;
        int r = pk & 15;
        const __half* row = g_hallh + ((size_t)r * Nn + s) * D;
        uint2 raw = ((const uint2*)row)[lane];
        __half2 h0 = *(__half2*)&raw.x;
        __half2 h1 = *(__half2*)&raw.y;
        float2 f0 = __half22float2(h0);
        float2 f1 = __half22float2(h1);
        v[i] = make_float4(f0.x * gc, f0.y * gc, f1.x * gc, f1.y * gc);
    }
#pragma unroll
    for (int i = 0; i < EPW; i++) {
        if (i >= cnt) break;
        float* o = out + (size_t)dv[i] * D + lane * 4;
        asm volatile("red.global.add.v4.f32 [%0], {%1,%2,%3,%4};"
                     :: "l"(o), "f"(v[i].x), "f"(v[i].y), "f"(v[i].z), "f"(v[i].w)
                     : "memory");
    }
}

// ---------------------------------------------------------------------------
__global__ void round_kernel(const float* __restrict__ x, float* __restrict__ y,
                             size_t n)
{
    size_t i = (size_t)blockIdx.x * blockDim.x + threadIdx.x;
    if (i < n) y[i] = f2tf32f(x[i]);
}

__global__ void round_wT_kernel(const float* __restrict__ W,
                                float* __restrict__ out, int R)
{
    int i = blockIdx.x * blockDim.x + threadIdx.x;
    if (i >= R * D * D) return;
    int r = i / (D * D);
    int e = (i / D) & (D - 1);
    int d = i & (D - 1);
    out[i] = f2tf32f(W[(size_t)r * D * D + (size_t)d * D + e]);
}

// gate[n][r] = sigmoid(dot(h[n], gw[r])); one warp per node
__global__ void glog_kernel(const float* __restrict__ h, const float* __restrict__ gw,
                            int Nn)
{
    int warp = (int)((blockIdx.x * blockDim.x + threadIdx.x) >> 5);
    int lane = threadIdx.x & 31;
    if (warp >= Nn) return;
    float4 hv = ((const float4*)(h + (size_t)warp * D))[lane];
    float mine = 0.f;
#pragma unroll
    for (int r = 0; r < NRELS; r++) {
        float4 gv = ((const float4*)(gw + r * D))[lane];
        float dot = hv.x * gv.x + hv.y * gv.y + hv.z * gv.z + hv.w * gv.w;
#pragma unroll
        for (int off = 16; off > 0; off >>= 1)
            dot += __shfl_down_sync(0xffffffffu, dot, off);
        dot = __shfl_sync(0xffffffffu, dot, 0);
        if (lane == r) mine = dot;
    }
    if (lane < NRELS)
        g_gate[(size_t)warp * NRELS + lane] = 1.f / (1.f + expf(-mine));
}

// relu in place + tf32-rounded copy
__global__ void relu_round_kernel(float* __restrict__ x, float* __restrict__ y,
                                  size_t n)
{
    size_t i = (size_t)blockIdx.x * blockDim.x + threadIdx.x;
    if (i >= n) return;
    float v = fmaxf(x[i], 0.f);
    x[i] = v;
    y[i] = f2tf32f(v);
}

// ---------------------------------------------------------------------------
extern "C" void kernel_launch(void* const* d_in, const int* in_sizes, int n_in,
                              void* d_out, int out_size)
{
    const float* h    = (const float*)d_in[0];
    const float* norm = (const float*)d_in[1];
    const float* W0   = (const float*)d_in[2];
    const float* b0   = (const float*)d_in[3];
    const float* lw0  = (const float*)d_in[4];
    const float* gw0  = (const float*)d_in[5];
    const float* W1   = (const float*)d_in[6];
    const float* b1   = (const float*)d_in[7];
    const float* lw1  = (const float*)d_in[8];
    const float* gw1  = (const float*)d_in[9];
    const int*   src  = (const int*)d_in[10];
    const int*   dst  = (const int*)d_in[11];
    const int*   rel  = (const int*)d_in[12];
    float* out = (float*)d_out;

    int Nn = in_sizes[0] / D;
    int E  = in_sizes[10];
    int NT = (Nn + 127) / 128;
    size_t nElem = (size_t)Nn * D;
    int mtiles = (Nn + 255) / 256;

    cudaFuncSetAttribute(gemm_v2<0>, cudaFuncAttributeMaxDynamicSharedMemorySize,
                         GEMM_SMEM);
    cudaFuncSetAttribute(gemm_v2<1>, cudaFuncAttributeMaxDynamicSharedMemorySize,
                         GEMM_SMEM);

    __half* hallh;
    float *h1_ptr, *atf, *wt0, *wt1, *lwt0, *lwt1;
    int *cnt, *cur;
    cudaGetSymbolAddress((void**)&hallh, g_hallh);
    cudaGetSymbolAddress((void**)&h1_ptr, g_h1);
    cudaGetSymbolAddress((void**)&atf, g_atf);
    cudaGetSymbolAddress((void**)&wt0, g_wt0);
    cudaGetSymbolAddress((void**)&wt1, g_wt1);
    cudaGetSymbolAddress((void**)&lwt0, g_lwt0);
    cudaGetSymbolAddress((void**)&lwt1, g_lwt1);
    cudaGetSymbolAddress((void**)&cnt, g_cnt);
    cudaGetSymbolAddress((void**)&cur, g_cur);

    const int scatterBlocks = (((E + EPW - 1) / EPW) * 32 + 255) / 256;

    // ---- preprocess (shared by both layers) --------------------------------
    cudaMemsetAsync(cnt, 0, NBMAX * sizeof(int));
    cudaMemsetAsync(cur, 0, NBMAX * sizeof(int));
    hist_kernel<<<(E + 255) / 256, 256>>>(src, rel, E, NT);
    scan_kernel<<<1, 1024>>>(NRELS * NT);
    fill_kernel<<<(E + 255) / 256, 256>>>(src, dst, rel, norm, E, NT);
    round_wT_kernel<<<(NRELS * D * D + 255) / 256, 256>>>(W0, wt0, NRELS);
    round_wT_kernel<<<(NRELS * D * D + 255) / 256, 256>>>(W1, wt1, NRELS);
    round_wT_kernel<<<(D * D + 255) / 256, 256>>>(lw0, lwt0, 1);
    round_wT_kernel<<<(D * D + 255) / 256, 256>>>(lw1, lwt1, 1);
    round_kernel<<<(int)((nElem + 255) / 256), 256>>>(h, atf, nElem);

    // ================= Layer 0 ==============================================
    glog_kernel<<<(Nn * 32 + 255) / 256, 256>>>(h, gw0, Nn);
    gemm_v2<0><<<dim3(mtiles, 1), 512, GEMM_SMEM>>>(atf, lwt0, h1_ptr,
                                                    0, 1, Nn, b0);
    gemm_v2<1><<<dim3(mtiles, 2), 512, GEMM_SMEM>>>(atf, wt0, hallh,
                                                    (size_t)Nn * D, NRELS / 2,
                                                    Nn, nullptr);
    scatter_kernel<<<scatterBlocks, 256>>>(h1_ptr, E, Nn);
    relu_round_kernel<<<(int)((nElem + 255) / 256), 256>>>(h1_ptr, atf, nElem);

    // ================= Layer 1 ==============================================
    glog_kernel<<<(Nn * 32 + 255) / 256, 256>>>(h1_ptr, gw1, Nn);
    gemm_v2<0><<<dim3(mtiles, 1), 512, GEMM_SMEM>>>(atf, lwt1, out,
                                                    0, 1, Nn, b1);
    gemm_v2<1><<<dim3(mtiles, 2), 512, GEMM_SMEM>>>(atf, wt1, hallh,
                                                    (size_t)Nn * D, NRELS / 2,
                                                    Nn, nullptr);
    scatter_kernel<<<scatterBlocks, 256>>>(out, E, Nn);
}

// round 14
// speedup vs baseline: 1.3839x; 1.2319x over previous
#include <cuda_runtime.h>
#include <cuda_fp16.h>
#include <math.h>
#include <stdint.h>

#define D 128
#define NRELS 16
#define MAXN 50000
#define MAXE 800000
#define MAXNT 400
#define NBMAX (NRELS * MAXNT)

// ---------------- scratch (__device__ globals) ------------------------------
__device__ __half g_hallh[(size_t)NRELS * MAXN * D]; // [r][n][d] fp16 messages
__device__ float g_gate[(size_t)MAXN * NRELS];       // sigmoid(glog), pk=s*16+r
__device__ float g_h1[(size_t)MAXN * D];             // layer-0 out (fp32)
__device__ __half g_ah[(size_t)MAXN * D];            // layer input fp16
__device__ __half g_wh0[(size_t)NRELS * D * D];      // W0^T fp16 [r][e][d]
__device__ __half g_wh1[(size_t)NRELS * D * D];
__device__ __half g_lwh0[(size_t)D * D];
__device__ __half g_lwh1[(size_t)D * D];
__device__ int   g_cnt[NBMAX];
__device__ int   g_cur[NBMAX];
__device__ int   g_rp[NBMAX + 1];
__device__ int   g_spk[MAXE];                        // sorted src*16+rel
__device__ int   g_sdst[MAXE];                       // sorted dst
__device__ float g_snorm[MAXE];                      // sorted norm

__device__ __forceinline__ uint32_t smem_u32(const void* p) {
    uint32_t a;
    asm("{ .reg .u64 t; cvta.to.shared.u64 t, %1; cvt.u32.u64 %0, t; }"
        : "=r"(a) : "l"(p));
    return a;
}
__device__ __forceinline__ void cp16(uint32_t dst, const void* src, int srcBytes) {
    asm volatile("cp.async.cg.shared.global [%0], [%1], 16, %2;"
                 :: "r"(dst), "l"(src), "r"(srcBytes) : "memory");
}
#define CP_COMMIT() asm volatile("cp.async.commit_group;" ::: "memory")
#define CP_WAIT0()  asm volatile("cp.async.wait_group 0;" ::: "memory")

// ---------------------------------------------------------------------------
// fp16 HMMA GEMM: 512 threads, BM=256, BN=128, 16 warps (4m x 4n),
// warp tile 64x32, mma.sync.m16n8k16.f32.f16.f16.f32 (2x tf32 rate).
// A resident full-K fp16; B[r] full tiles double-buffered via cp.async.
// HALF_OUT=1: C fp16 (hall). HALF_OUT=0: C fp32 + bias.
// ---------------------------------------------------------------------------
#define SROW_H 136                        // halves per row (128 + 8 pad)
#define ROWB   (SROW_H * 2)               // 272 bytes
#define SM_AH  (256 * ROWB)               // 69632
#define SM_BH  (128 * ROWB)               // 34816
#define GEMM_SMEM (SM_AH + 2 * SM_BH)     // 139264

template <int HALF_OUT>
__global__ __launch_bounds__(512)
void gemm_h(const __half* __restrict__ A, const __half* __restrict__ B,
            void* __restrict__ C0v, size_t strideC, int Rper, int M,
            const float* __restrict__ bias)
{
    extern __shared__ char smem[];
    const uint32_t sA  = smem_u32(smem);
    const uint32_t sB0 = sA + SM_AH;
    const uint32_t sB1 = sB0 + SM_BH;

    const int tid  = threadIdx.x;
    const int lane = tid & 31;
    const int wid  = tid >> 5;
    const int warp_m = wid >> 2;        // 0..3 (64 rows)
    const int warp_n = wid & 3;         // 0..3 (32 cols)
    const int g = lane >> 2;            // 0..7
    const int c = lane & 3;             // 0..3
    const int mBase = blockIdx.x * 256;
    const int rBase = blockIdx.y * Rper;

    // ---- stage A (256 rows x 128 halves): 4096 16B chunks, 8/thread -------
#pragma unroll
    for (int it = 0; it < 8; it++) {
        int i = tid + it * 512;
        int row = i >> 4;               // 0..255
        int ch  = i & 15;
        bool valid = (mBase + row) < M;
        const __half* src = A + (valid ? ((size_t)(mBase + row) * D + ch * 8) : 0);
        cp16(sA + (uint32_t)(row * ROWB + ch * 16), src, valid ? 16 : 0);
    }
    // ---- stage B(rBase): 2048 chunks, 4/thread -----------------------------
    {
        const __half* Bc = B + (size_t)rBase * D * D;
#pragma unroll
        for (int it = 0; it < 4; it++) {
            int i = tid + it * 512;
            int row = i >> 4;           // 0..127
            int ch  = i & 15;
            cp16(sB0 + (uint32_t)(row * ROWB + ch * 16),
                 Bc + (size_t)row * D + ch * 8, 16);
        }
    }
    CP_COMMIT();
    CP_WAIT0();
    __syncthreads();

    const uint32_t aBase = sA + (uint32_t)(warp_m * 64) * ROWB;

    for (int r = 0; r < Rper; r++) {
        const uint32_t sCur = (r & 1) ? sB1 : sB0;
        const uint32_t sNxt = (r & 1) ? sB0 : sB1;

        if (r + 1 < Rper) {   // prefetch B(r+1)
            const __half* Bc = B + (size_t)(rBase + r + 1) * D * D;
#pragma unroll
            for (int it = 0; it < 4; it++) {
                int i = tid + it * 512;
                int row = i >> 4;
                int ch  = i & 15;
                cp16(sNxt + (uint32_t)(row * ROWB + ch * 16),
                     Bc + (size_t)row * D + ch * 8, 16);
            }
            CP_COMMIT();
        }

        float acc[4][4][4];
#pragma unroll
        for (int mi = 0; mi < 4; mi++)
#pragma unroll
            for (int ni = 0; ni < 4; ni++)
#pragma unroll
                for (int f = 0; f < 4; f++) acc[mi][ni][f] = 0.f;

        const uint32_t bBase = sCur + (uint32_t)(warp_n * 32) * ROWB;

#pragma unroll
        for (int ks = 0; ks < 8; ks++) {
            const int kb = ks * 16;     // k offset in halves
            uint32_t af[4][4], bf[4][2];
#pragma unroll
            for (int mi = 0; mi < 4; mi++) {
                uint32_t a0 = aBase + (uint32_t)((mi * 16 + g) * ROWB + (kb + 2 * c) * 2);
                asm volatile("ld.shared.b32 %0, [%1];"      : "=r"(af[mi][0]) : "r"(a0));
                asm volatile("ld.shared.b32 %0, [%1+16];"   : "=r"(af[mi][2]) : "r"(a0));
                uint32_t a1 = a0 + 8u * ROWB;
                asm volatile("ld.shared.b32 %0, [%1];"      : "=r"(af[mi][1]) : "r"(a1));
                asm volatile("ld.shared.b32 %0, [%1+16];"   : "=r"(af[mi][3]) : "r"(a1));
            }
#pragma unroll
            for (int ni = 0; ni < 4; ni++) {
                uint32_t b0 = bBase + (uint32_t)((ni * 8 + g) * ROWB + (kb + 2 * c) * 2);
                asm volatile("ld.shared.b32 %0, [%1];"      : "=r"(bf[ni][0]) : "r"(b0));
                asm volatile("ld.shared.b32 %0, [%1+16];"   : "=r"(bf[ni][1]) : "r"(b0));
            }
#pragma unroll
            for (int mi = 0; mi < 4; mi++)
#pragma unroll
                for (int ni = 0; ni < 4; ni++) {
                    asm volatile(
                        "mma.sync.aligned.m16n8k16.row.col.f32.f16.f16.f32 "
                        "{%0,%1,%2,%3}, {%4,%5,%6,%7}, {%8,%9}, {%0,%1,%2,%3};\n"
                        : "+f"(acc[mi][ni][0]), "+f"(acc[mi][ni][1]),
                          "+f"(acc[mi][ni][2]), "+f"(acc[mi][ni][3])
                        : "r"(af[mi][0]), "r"(af[mi][1]),
                          "r"(af[mi][2]), "r"(af[mi][3]),
                          "r"(bf[ni][0]), "r"(bf[ni][1]));
                }
        }

        // ---- epilogue ------------------------------------------------------
        const int rr = rBase + r;
#pragma unroll
        for (int mi = 0; mi < 4; mi++) {
            const int row0 = mBase + warp_m * 64 + mi * 16 + g;
            const int row1 = row0 + 8;
#pragma unroll
            for (int ni = 0; ni < 4; ni++) {
                const int col = warp_n * 32 + ni * 8 + c * 2;
                if (HALF_OUT) {
                    __half* C = (__half*)C0v + (size_t)rr * strideC;
                    if (row0 < M)
                        *(__half2*)(C + (size_t)row0 * D + col) =
                            __floats2half2_rn(acc[mi][ni][0], acc[mi][ni][1]);
                    if (row1 < M)
                        *(__half2*)(C + (size_t)row1 * D + col) =
                            __floats2half2_rn(acc[mi][ni][2], acc[mi][ni][3]);
                } else {
                    float* C = (float*)C0v + (size_t)rr * strideC;
                    float bx = 0.f, by = 0.f;
                    if (bias != nullptr) { bx = bias[col]; by = bias[col + 1]; }
                    if (row0 < M)
                        *(float2*)(C + (size_t)row0 * D + col) =
                            make_float2(acc[mi][ni][0] + bx, acc[mi][ni][1] + by);
                    if (row1 < M)
                        *(float2*)(C + (size_t)row1 * D + col) =
                            make_float2(acc[mi][ni][2] + bx, acc[mi][ni][3] + by);
                }
            }
        }

        if (r + 1 < Rper) {
            CP_WAIT0();
            __syncthreads();
        }
    }
}

// ---------------------------------------------------------------------------
// preprocessing: bucket edges by (rel, src>>7); pack sorted meta arrays
// ---------------------------------------------------------------------------
__global__ void hist_kernel(const int* __restrict__ src, const int* __restrict__ rel,
                            int E, int NT)
{
    int e = blockIdx.x * blockDim.x + threadIdx.x;
    if (e < E) atomicAdd(&g_cnt[rel[e] * NT + (src[e] >> 7)], 1);
}

__global__ void scan_kernel(int nb)
{
    __shared__ int part[1024];
    const int tid = threadIdx.x;
    const int per = (nb + 1023) / 1024;
    const int base = tid * per;
    int s = 0;
    for (int i = 0; i < per; i++)
        if (base + i < nb) s += g_cnt[base + i];
    part[tid] = s;
    __syncthreads();
    for (int off = 1; off < 1024; off <<= 1) {
        int v = (tid >= off) ? part[tid - off] : 0;
        __syncthreads();
        part[tid] += v;
        __syncthreads();
    }
    int run = (tid > 0) ? part[tid - 1] : 0;
    for (int i = 0; i < per; i++) {
        if (base + i < nb) {
            g_rp[base + i] = run;
            run += g_cnt[base + i];
        }
    }
    if (tid == 1023) g_rp[nb] = part[1023];
}

__global__ void fill_kernel(const int* __restrict__ src, const int* __restrict__ dst,
                            const int* __restrict__ rel, const float* __restrict__ norm,
                            int E, int NT)
{
    int e = blockIdx.x * blockDim.x + threadIdx.x;
    if (e >= E) return;
    int key = rel[e] * NT + (src[e] >> 7);
    int pos = g_rp[key] + atomicAdd(&g_cur[key], 1);
    g_spk[pos]   = src[e] * NRELS + rel[e];
    g_sdst[pos]  = dst[e];
    g_snorm[pos] = norm[e];
}

// ---------------------------------------------------------------------------
// Edge scatter (R13-proven): EPW=4 edges/warp, fp16 hall reads, fp32 red.v4
// ---------------------------------------------------------------------------
#define EPW 4
__global__ void scatter_kernel(float* __restrict__ out, int E, int Nn)
{
    int warp = (int)((blockIdx.x * blockDim.x + threadIdx.x) >> 5);
    int lane = threadIdx.x & 31;
    int base = warp * EPW;
    if (base >= E) return;

    float4 v[EPW];
    int dv[EPW];
    int cnt = min(EPW, E - base);
#pragma unroll
    for (int i = 0; i < EPW; i++) {
        if (i >= cnt) break;
        int idx = base + i;
        int pk = __ldg(g_spk + idx);
        dv[i]  = __ldg(g_sdst + idx);
        float nm = __ldg(g_snorm + idx);
        float gc = nm * __ldg(g_gate + pk);
        int s = pk >> 4;
        int r = pk & 15;
        const __half* row = g_hallh + ((size_t)r * Nn + s) * D;
        uint2 raw = ((const uint2*)row)[lane];
        __half2 h0 = *(__half2*)&raw.x;
        __half2 h1 = *(__half2*)&raw.y;
        float2 f0 = __half22float2(h0);
        float2 f1 = __half22float2(h1);
        v[i] = make_float4(f0.x * gc, f0.y * gc, f1.x * gc, f1.y * gc);
    }
#pragma unroll
    for (int i = 0; i < EPW; i++) {
        if (i >= cnt) break;
        float* o = out + (size_t)dv[i] * D + lane * 4;
        asm volatile("red.global.add.v4.f32 [%0], {%1,%2,%3,%4};"
                     :: "l"(o), "f"(v[i].x), "f"(v[i].y), "f"(v[i].z), "f"(v[i].w)
                     : "memory");
    }
}

// ---------------------------------------------------------------------------
__global__ void tohalf_kernel(const float* __restrict__ x, __half* __restrict__ y,
                              size_t n)
{
    size_t i = (size_t)blockIdx.x * blockDim.x + threadIdx.x;
    if (i < n) y[i] = __float2half(x[i]);
}

// W[r][d][e] -> out[r][e][d] fp16
__global__ void wT_half_kernel(const float* __restrict__ W,
                               __half* __restrict__ out, int R)
{
    int i = blockIdx.x * blockDim.x + threadIdx.x;
    if (i >= R * D * D) return;
    int r = i / (D * D);
    int e = (i / D) & (D - 1);
    int d = i & (D - 1);
    out[i] = __float2half(W[(size_t)r * D * D + (size_t)d * D + e]);
}

// gate[n][r] = sigmoid(dot(h[n], gw[r])); one warp per node
__global__ void glog_kernel(const float* __restrict__ h, const float* __restrict__ gw,
                            int Nn)
{
    int warp = (int)((blockIdx.x * blockDim.x + threadIdx.x) >> 5);
    int lane = threadIdx.x & 31;
    if (warp >= Nn) return;
    float4 hv = ((const float4*)(h + (size_t)warp * D))[lane];
    float mine = 0.f;
#pragma unroll
    for (int r = 0; r < NRELS; r++) {
        float4 gv = ((const float4*)(gw + r * D))[lane];
        float dot = hv.x * gv.x + hv.y * gv.y + hv.z * gv.z + hv.w * gv.w;
#pragma unroll
        for (int off = 16; off > 0; off >>= 1)
            dot += __shfl_down_sync(0xffffffffu, dot, off);
        dot = __shfl_sync(0xffffffffu, dot, 0);
        if (lane == r) mine = dot;
    }
    if (lane < NRELS)
        g_gate[(size_t)warp * NRELS + lane] = 1.f / (1.f + expf(-mine));
}

// relu in place + fp16 copy
__global__ void relu_half_kernel(float* __restrict__ x, __half* __restrict__ y,
                                 size_t n)
{
    size_t i = (size_t)blockIdx.x * blockDim.x + threadIdx.x;
    if (i >= n) return;
    float v = fmaxf(x[i], 0.f);
    x[i] = v;
    y[i] = __float2half(v);
}

// ---------------------------------------------------------------------------
extern "C" void kernel_launch(void* const* d_in, const int* in_sizes, int n_in,
                              void* d_out, int out_size)
{
    const float* h    = (const float*)d_in[0];
    const float* norm = (const float*)d_in[1];
    const float* W0   = (const float*)d_in[2];
    const float* b0   = (const float*)d_in[3];
    const float* lw0  = (const float*)d_in[4];
    const float* gw0  = (const float*)d_in[5];
    const float* W1   = (const float*)d_in[6];
    const float* b1   = (const float*)d_in[7];
    const float* lw1  = (const float*)d_in[8];
    const float* gw1  = (const float*)d_in[9];
    const int*   src  = (const int*)d_in[10];
    const int*   dst  = (const int*)d_in[11];
    const int*   rel  = (const int*)d_in[12];
    float* out = (float*)d_out;

    int Nn = in_sizes[0] / D;
    int E  = in_sizes[10];
    int NT = (Nn + 127) / 128;
    size_t nElem = (size_t)Nn * D;
    int mtiles = (Nn + 255) / 256;

    cudaFuncSetAttribute(gemm_h<0>, cudaFuncAttributeMaxDynamicSharedMemorySize,
                         GEMM_SMEM);
    cudaFuncSetAttribute(gemm_h<1>, cudaFuncAttributeMaxDynamicSharedMemorySize,
                         GEMM_SMEM);

    __half *hallh, *ah, *wh0, *wh1, *lwh0, *lwh1;
    float *h1_ptr;
    int *cnt, *cur;
    cudaGetSymbolAddress((void**)&hallh, g_hallh);
    cudaGetSymbolAddress((void**)&ah, g_ah);
    cudaGetSymbolAddress((void**)&wh0, g_wh0);
    cudaGetSymbolAddress((void**)&wh1, g_wh1);
    cudaGetSymbolAddress((void**)&lwh0, g_lwh0);
    cudaGetSymbolAddress((void**)&lwh1, g_lwh1);
    cudaGetSymbolAddress((void**)&h1_ptr, g_h1);
    cudaGetSymbolAddress((void**)&cnt, g_cnt);
    cudaGetSymbolAddress((void**)&cur, g_cur);

    const int scatterBlocks = (((E + EPW - 1) / EPW) * 32 + 255) / 256;

    // ---- preprocess (shared by both layers) --------------------------------
    cudaMemsetAsync(cnt, 0, NBMAX * sizeof(int));
    cudaMemsetAsync(cur, 0, NBMAX * sizeof(int));
    hist_kernel<<<(E + 255) / 256, 256>>>(src, rel, E, NT);
    scan_kernel<<<1, 1024>>>(NRELS * NT);
    fill_kernel<<<(E + 255) / 256, 256>>>(src, dst, rel, norm, E, NT);
    wT_half_kernel<<<(NRELS * D * D + 255) / 256, 256>>>(W0, wh0, NRELS);
    wT_half_kernel<<<(NRELS * D * D + 255) / 256, 256>>>(W1, wh1, NRELS);
    wT_half_kernel<<<(D * D + 255) / 256, 256>>>(lw0, lwh0, 1);
    wT_half_kernel<<<(D * D + 255) / 256, 256>>>(lw1, lwh1, 1);
    tohalf_kernel<<<(int)((nElem + 255) / 256), 256>>>(h, ah, nElem);

    // ================= Layer 0 ==============================================
    glog_kernel<<<(Nn * 32 + 255) / 256, 256>>>(h, gw0, Nn);
    gemm_h<0><<<dim3(mtiles, 1), 512, GEMM_SMEM>>>(ah, lwh0, h1_ptr,
                                                   0, 1, Nn, b0);
    gemm_h<1><<<dim3(mtiles, 2), 512, GEMM_SMEM>>>(ah, wh0, hallh,
                                                   (size_t)Nn * D, NRELS / 2,
                                                   Nn, nullptr);
    scatter_kernel<<<scatterBlocks, 256>>>(h1_ptr, E, Nn);
    relu_half_kernel<<<(int)((nElem + 255) / 256), 256>>>(h1_ptr, ah, nElem);

    // ================= Layer 1 ==============================================
    glog_kernel<<<(Nn * 32 + 255) / 256, 256>>>(h1_ptr, gw1, Nn);
    gemm_h<0><<<dim3(mtiles, 1), 512, GEMM_SMEM>>>(ah, lwh1, out,
                                                   0, 1, Nn, b1);
    gemm_h<1><<<dim3(mtiles, 2), 512, GEMM_SMEM>>>(ah, wh1, hallh,
                                                   (size_t)Nn * D, NRELS / 2,
                                                   Nn, nullptr);
    scatter_kernel<<<scatterBlocks, 256>>>(out, E, Nn);
}

// round 15
// speedup vs baseline: 1.4383x; 1.0393x over previous
#include <cuda_runtime.h>
#include <cuda_fp16.h>
#include <math.h>
#include <stdint.h>

#define D 128
#define NRELS 16
#define MAXN 50000
#define MAXE 800000
#define MAXNT 400
#define NBMAX (NRELS * MAXNT)

// ---------------- scratch (__device__ globals) ------------------------------
__device__ __half g_hallh[(size_t)NRELS * MAXN * D]; // [r][n][d] fp16 messages
__device__ float g_gate[(size_t)MAXN * NRELS];       // sigmoid(glog), pk=s*16+r
__device__ float g_h1[(size_t)MAXN * D];             // layer-0 out (fp32)
__device__ __half g_ah[(size_t)MAXN * D];            // layer input fp16
__device__ __half g_wh0[(size_t)NRELS * D * D];      // W0^T fp16 [r][e][d]
__device__ __half g_wh1[(size_t)NRELS * D * D];
__device__ __half g_lwh0[(size_t)D * D];
__device__ __half g_lwh1[(size_t)D * D];
__device__ int   g_cnt[NBMAX];
__device__ int   g_cur[NBMAX];
__device__ int   g_rp[NBMAX + 1];
__device__ int   g_spk[MAXE];                        // sorted src*16+rel
__device__ int   g_sdst[MAXE];                       // sorted dst
__device__ float g_snorm[MAXE];                      // sorted norm

__device__ __forceinline__ uint32_t smem_u32(const void* p) {
    uint32_t a;
    asm("{ .reg .u64 t; cvta.to.shared.u64 t, %1; cvt.u32.u64 %0, t; }"
        : "=r"(a) : "l"(p));
    return a;
}
__device__ __forceinline__ void cp16(uint32_t dst, const void* src, int srcBytes) {
    asm volatile("cp.async.cg.shared.global [%0], [%1], 16, %2;"
                 :: "r"(dst), "l"(src), "r"(srcBytes) : "memory");
}
#define CP_COMMIT() asm volatile("cp.async.commit_group;" ::: "memory")
#define CP_WAIT0()  asm volatile("cp.async.wait_group 0;" ::: "memory")

// ---------------------------------------------------------------------------
// fp16 HMMA GEMM: 512 threads, BM=256, BN=128, 16 warps (4m x 4n),
// warp tile 64x32, mma.sync.m16n8k16 with ldmatrix.x4 fragment loads
// (6 LDSM + 16 MMA per k-step vs 24 LDS + 16 MMA -> MMA issue share up).
// HALF_OUT=1: C fp16 (hall). HALF_OUT=0: C fp32 + bias.
// ---------------------------------------------------------------------------
#define SROW_H 136                        // halves per row (128 + 8 pad)
#define ROWB   (SROW_H * 2)               // 272 bytes
#define SM_AH  (256 * ROWB)               // 69632
#define SM_BH  (128 * ROWB)               // 34816
#define GEMM_SMEM (SM_AH + 2 * SM_BH)     // 139264

template <int HALF_OUT>
__global__ __launch_bounds__(512)
void gemm_h(const __half* __restrict__ A, const __half* __restrict__ B,
            void* __restrict__ C0v, size_t strideC, int Rper, int M,
            const float* __restrict__ bias)
{
    extern __shared__ char smem[];
    const uint32_t sA  = smem_u32(smem);
    const uint32_t sB0 = sA + SM_AH;
    const uint32_t sB1 = sB0 + SM_BH;

    const int tid  = threadIdx.x;
    const int lane = tid & 31;
    const int wid  = tid >> 5;
    const int warp_m = wid >> 2;        // 0..3 (64 rows)
    const int warp_n = wid & 3;         // 0..3 (32 cols)
    const int g = lane >> 2;            // 0..7
    const int c = lane & 3;             // 0..3
    const int mBase = blockIdx.x * 256;
    const int rBase = blockIdx.y * Rper;

    // ldmatrix per-lane source coordinates
    const int aRow = lane & 15;               // row within 16-row tile
    const int aK   = (lane >> 4) * 8;         // k-half select
    const int bRow = (lane & 7) + ((lane >> 4) << 3);  // n row (tile pair)
    const int bK   = ((lane >> 3) & 1) * 8;   // k-half select

    // ---- stage A (256 rows x 128 halves): 4096 16B chunks, 8/thread -------
#pragma unroll
    for (int it = 0; it < 8; it++) {
        int i = tid + it * 512;
        int row = i >> 4;               // 0..255
        int ch  = i & 15;
        bool valid = (mBase + row) < M;
        const __half* src = A + (valid ? ((size_t)(mBase + row) * D + ch * 8) : 0);
        cp16(sA + (uint32_t)(row * ROWB + ch * 16), src, valid ? 16 : 0);
    }
    // ---- stage B(rBase): 2048 chunks, 4/thread -----------------------------
    {
        const __half* Bc = B + (size_t)rBase * D * D;
#pragma unroll
        for (int it = 0; it < 4; it++) {
            int i = tid + it * 512;
            int row = i >> 4;           // 0..127
            int ch  = i & 15;
            cp16(sB0 + (uint32_t)(row * ROWB + ch * 16),
                 Bc + (size_t)row * D + ch * 8, 16);
        }
    }
    CP_COMMIT();
    CP_WAIT0();
    __syncthreads();

    const uint32_t aBase = sA + (uint32_t)(warp_m * 64) * ROWB;

    for (int r = 0; r < Rper; r++) {
        const uint32_t sCur = (r & 1) ? sB1 : sB0;
        const uint32_t sNxt = (r & 1) ? sB0 : sB1;

        if (r + 1 < Rper) {   // prefetch B(r+1)
            const __half* Bc = B + (size_t)(rBase + r + 1) * D * D;
#pragma unroll
            for (int it = 0; it < 4; it++) {
                int i = tid + it * 512;
                int row = i >> 4;
                int ch  = i & 15;
                cp16(sNxt + (uint32_t)(row * ROWB + ch * 16),
                     Bc + (size_t)row * D + ch * 8, 16);
            }
            CP_COMMIT();
        }

        float acc[4][4][4];
#pragma unroll
        for (int mi = 0; mi < 4; mi++)
#pragma unroll
            for (int ni = 0; ni < 4; ni++)
#pragma unroll
                for (int f = 0; f < 4; f++) acc[mi][ni][f] = 0.f;

        const uint32_t bBase = sCur + (uint32_t)(warp_n * 32) * ROWB;

#pragma unroll
        for (int ks = 0; ks < 8; ks++) {
            const int kb = ks * 16;     // k offset in halves
            uint32_t af[4][4], bf[4][2];
#pragma unroll
            for (int mi = 0; mi < 4; mi++) {
                uint32_t addr = aBase
                    + (uint32_t)((mi * 16 + aRow) * ROWB)
                    + (uint32_t)((kb + aK) * 2);
                asm volatile(
                    "ldmatrix.sync.aligned.m8n8.x4.shared.b16 {%0,%1,%2,%3}, [%4];"
                    : "=r"(af[mi][0]), "=r"(af[mi][1]),
                      "=r"(af[mi][2]), "=r"(af[mi][3])
                    : "r"(addr));
            }
#pragma unroll
            for (int np = 0; np < 2; np++) {
                uint32_t addr = bBase
                    + (uint32_t)((np * 16 + bRow) * ROWB)
                    + (uint32_t)((kb + bK) * 2);
                asm volatile(
                    "ldmatrix.sync.aligned.m8n8.x4.shared.b16 {%0,%1,%2,%3}, [%4];"
                    : "=r"(bf[np * 2][0]), "=r"(bf[np * 2][1]),
                      "=r"(bf[np * 2 + 1][0]), "=r"(bf[np * 2 + 1][1])
                    : "r"(addr));
            }
#pragma unroll
            for (int mi = 0; mi < 4; mi++)
#pragma unroll
                for (int ni = 0; ni < 4; ni++) {
                    asm volatile(
                        "mma.sync.aligned.m16n8k16.row.col.f32.f16.f16.f32 "
                        "{%0,%1,%2,%3}, {%4,%5,%6,%7}, {%8,%9}, {%0,%1,%2,%3};\n"
                        : "+f"(acc[mi][ni][0]), "+f"(acc[mi][ni][1]),
                          "+f"(acc[mi][ni][2]), "+f"(acc[mi][ni][3])
                        : "r"(af[mi][0]), "r"(af[mi][1]),
                          "r"(af[mi][2]), "r"(af[mi][3]),
                          "r"(bf[ni][0]), "r"(bf[ni][1]));
                }
        }

        // ---- epilogue ------------------------------------------------------
        const int rr = rBase + r;
#pragma unroll
        for (int mi = 0; mi < 4; mi++) {
            const int row0 = mBase + warp_m * 64 + mi * 16 + g;
            const int row1 = row0 + 8;
#pragma unroll
            for (int ni = 0; ni < 4; ni++) {
                const int col = warp_n * 32 + ni * 8 + c * 2;
                if (HALF_OUT) {
                    __half* C = (__half*)C0v + (size_t)rr * strideC;
                    if (row0 < M)
                        *(__half2*)(C + (size_t)row0 * D + col) =
                            __floats2half2_rn(acc[mi][ni][0], acc[mi][ni][1]);
                    if (row1 < M)
                        *(__half2*)(C + (size_t)row1 * D + col) =
                            __floats2half2_rn(acc[mi][ni][2], acc[mi][ni][3]);
                } else {
                    float* C = (float*)C0v + (size_t)rr * strideC;
                    float bx = 0.f, by = 0.f;
                    if (bias != nullptr) { bx = bias[col]; by = bias[col + 1]; }
                    if (row0 < M)
                        *(float2*)(C + (size_t)row0 * D + col) =
                            make_float2(acc[mi][ni][0] + bx, acc[mi][ni][1] + by);
                    if (row1 < M)
                        *(float2*)(C + (size_t)row1 * D + col) =
                            make_float2(acc[mi][ni][2] + bx, acc[mi][ni][3] + by);
                }
            }
        }

        if (r + 1 < Rper) {
            CP_WAIT0();
            __syncthreads();
        }
    }
}

// ---------------------------------------------------------------------------
// preprocessing: bucket edges by (rel, src>>7); pack sorted meta arrays
// ---------------------------------------------------------------------------
__global__ void hist_kernel(const int* __restrict__ src, const int* __restrict__ rel,
                            int E, int NT)
{
    int e = blockIdx.x * blockDim.x + threadIdx.x;
    if (e < E) atomicAdd(&g_cnt[rel[e] * NT + (src[e] >> 7)], 1);
}

__global__ void scan_kernel(int nb)
{
    __shared__ int part[1024];
    const int tid = threadIdx.x;
    const int per = (nb + 1023) / 1024;
    const int base = tid * per;
    int s = 0;
    for (int i = 0; i < per; i++)
        if (base + i < nb) s += g_cnt[base + i];
    part[tid] = s;
    __syncthreads();
    for (int off = 1; off < 1024; off <<= 1) {
        int v = (tid >= off) ? part[tid - off] : 0;
        __syncthreads();
        part[tid] += v;
        __syncthreads();
    }
    int run = (tid > 0) ? part[tid - 1] : 0;
    for (int i = 0; i < per; i++) {
        if (base + i < nb) {
            g_rp[base + i] = run;
            run += g_cnt[base + i];
        }
    }
    if (tid == 1023) g_rp[nb] = part[1023];
}

__global__ void fill_kernel(const int* __restrict__ src, const int* __restrict__ dst,
                            const int* __restrict__ rel, const float* __restrict__ norm,
                            int E, int NT)
{
    int e = blockIdx.x * blockDim.x + threadIdx.x;
    if (e >= E) return;
    int key = rel[e] * NT + (src[e] >> 7);
    int pos = g_rp[key] + atomicAdd(&g_cur[key], 1);
    g_spk[pos]   = src[e] * NRELS + rel[e];
    g_sdst[pos]  = dst[e];
    g_snorm[pos] = norm[e];
}

// ---------------------------------------------------------------------------
// Edge scatter (R13-proven): EPW=4 edges/warp, fp16 hall reads, fp32 red.v4
// ---------------------------------------------------------------------------
#define EPW 4
__global__ void scatter_kernel(float* __restrict__ out, int E, int Nn)
{
    int warp = (int)((blockIdx.x * blockDim.x + threadIdx.x) >> 5);
    int lane = threadIdx.x & 31;
    int base = warp * EPW;
    if (base >= E) return;

    float4 v[EPW];
    int dv[EPW];
    int cnt = min(EPW, E - base);
#pragma unroll
    for (int i = 0; i < EPW; i++) {
        if (i >= cnt) break;
        int idx = base + i;
        int pk = __ldg(g_spk + idx);
        dv[i]  = __ldg(g_sdst + idx);
        float nm = __ldg(g_snorm + idx);
        float gc = nm * __ldg(g_gate + pk);
        int s = pk >> 4;
        int r = pk & 15;
        const __half* row = g_hallh + ((size_t)r * Nn + s) * D;
        uint2 raw = ((const uint2*)row)[lane];
        __half2 h0 = *(__half2*)&raw.x;
        __half2 h1 = *(__half2*)&raw.y;
        float2 f0 = __half22float2(h0);
        float2 f1 = __half22float2(h1);
        v[i] = make_float4(f0.x * gc, f0.y * gc, f1.x * gc, f1.y * gc);
    }
#pragma unroll
    for (int i = 0; i < EPW; i++) {
        if (i >= cnt) break;
        float* o = out + (size_t)dv[i] * D + lane * 4;
        asm volatile("red.global.add.v4.f32 [%0], {%1,%2,%3,%4};"
                     :: "l"(o), "f"(v[i].x), "f"(v[i].y), "f"(v[i].z), "f"(v[i].w)
                     : "memory");
    }
}

// ---------------------------------------------------------------------------
__global__ void tohalf_kernel(const float* __restrict__ x, __half* __restrict__ y,
                              size_t n)
{
    size_t i = (size_t)blockIdx.x * blockDim.x + threadIdx.x;
    if (i < n) y[i] = __float2half(x[i]);
}

// two weight tensors W[r][d][e] -> out[r][e][d] fp16 in one launch
__global__ void wT2_half_kernel(const float* __restrict__ Wa, __half* __restrict__ outa,
                                const float* __restrict__ Wb, __half* __restrict__ outb,
                                int R)
{
    int i = blockIdx.x * blockDim.x + threadIdx.x;
    int total = R * D * D;
    if (i >= 2 * total) return;
    const float* W = (i < total) ? Wa : Wb;
    __half* out = (i < total) ? outa : outb;
    int j = (i < total) ? i : i - total;
    int r = j / (D * D);
    int e = (j / D) & (D - 1);
    int d = j & (D - 1);
    out[j] = __float2half(W[(size_t)r * D * D + (size_t)d * D + e]);
}

// gate[n][r] = sigmoid(dot(h[n], gw[r])); one warp per node
__global__ void glog_kernel(const float* __restrict__ h, const float* __restrict__ gw,
                            int Nn)
{
    int warp = (int)((blockIdx.x * blockDim.x + threadIdx.x) >> 5);
    int lane = threadIdx.x & 31;
    if (warp >= Nn) return;
    float4 hv = ((const float4*)(h + (size_t)warp * D))[lane];
    float mine = 0.f;
#pragma unroll
    for (int r = 0; r < NRELS; r++) {
        float4 gv = ((const float4*)(gw + r * D))[lane];
        float dot = hv.x * gv.x + hv.y * gv.y + hv.z * gv.z + hv.w * gv.w;
#pragma unroll
        for (int off = 16; off > 0; off >>= 1)
            dot += __shfl_down_sync(0xffffffffu, dot, off);
        dot = __shfl_sync(0xffffffffu, dot, 0);
        if (lane == r) mine = dot;
    }
    if (lane < NRELS)
        g_gate[(size_t)warp * NRELS + lane] = 1.f / (1.f + expf(-mine));
}

// relu in place + fp16 copy
__global__ void relu_half_kernel(float* __restrict__ x, __half* __restrict__ y,
                                 size_t n)
{
    size_t i = (size_t)blockIdx.x * blockDim.x + threadIdx.x;
    if (i >= n) return;
    float v = fmaxf(x[i], 0.f);
    x[i] = v;
    y[i] = __float2half(v);
}

// ---------------------------------------------------------------------------
extern "C" void kernel_launch(void* const* d_in, const int* in_sizes, int n_in,
                              void* d_out, int out_size)
{
    const float* h    = (const float*)d_in[0];
    const float* norm = (const float*)d_in[1];
    const float* W0   = (const float*)d_in[2];
    const float* b0   = (const float*)d_in[3];
    const float* lw0  = (const float*)d_in[4];
    const float* gw0  = (const float*)d_in[5];
    const float* W1   = (const float*)d_in[6];
    const float* b1   = (const float*)d_in[7];
    const float* lw1  = (const float*)d_in[8];
    const float* gw1  = (const float*)d_in[9];
    const int*   src  = (const int*)d_in[10];
    const int*   dst  = (const int*)d_in[11];
    const int*   rel  = (const int*)d_in[12];
    float* out = (float*)d_out;

    int Nn = in_sizes[0] / D;
    int E  = in_sizes[10];
    int NT = (Nn + 127) / 128;
    size_t nElem = (size_t)Nn * D;
    int mtiles = (Nn + 255) / 256;

    cudaFuncSetAttribute(gemm_h<0>, cudaFuncAttributeMaxDynamicSharedMemorySize,
                         GEMM_SMEM);
    cudaFuncSetAttribute(gemm_h<1>, cudaFuncAttributeMaxDynamicSharedMemorySize,
                         GEMM_SMEM);

    __half *hallh, *ah, *wh0, *wh1, *lwh0, *lwh1;
    float *h1_ptr;
    int *cnt, *cur;
    cudaGetSymbolAddress((void**)&hallh, g_hallh);
    cudaGetSymbolAddress((void**)&ah, g_ah);
    cudaGetSymbolAddress((void**)&wh0, g_wh0);
    cudaGetSymbolAddress((void**)&wh1, g_wh1);
    cudaGetSymbolAddress((void**)&lwh0, g_lwh0);
    cudaGetSymbolAddress((void**)&lwh1, g_lwh1);
    cudaGetSymbolAddress((void**)&h1_ptr, g_h1);
    cudaGetSymbolAddress((void**)&cnt, g_cnt);
    cudaGetSymbolAddress((void**)&cur, g_cur);

    const int scatterBlocks = (((E + EPW - 1) / EPW) * 32 + 255) / 256;

    // ---- preprocess (shared by both layers) --------------------------------
    cudaMemsetAsync(cnt, 0, NBMAX * sizeof(int));
    cudaMemsetAsync(cur, 0, NBMAX * sizeof(int));
    hist_kernel<<<(E + 255) / 256, 256>>>(src, rel, E, NT);
    scan_kernel<<<1, 1024>>>(NRELS * NT);
    fill_kernel<<<(E + 255) / 256, 256>>>(src, dst, rel, norm, E, NT);
    wT2_half_kernel<<<(2 * NRELS * D * D + 255) / 256, 256>>>(W0, wh0, W1, wh1,
                                                              NRELS);
    wT2_half_kernel<<<(2 * D * D + 255) / 256, 256>>>(lw0, lwh0, lw1, lwh1, 1);
    tohalf_kernel<<<(int)((nElem + 255) / 256), 256>>>(h, ah, nElem);

    // ================= Layer 0 ==============================================
    glog_kernel<<<(Nn * 32 + 255) / 256, 256>>>(h, gw0, Nn);
    gemm_h<0><<<dim3(mtiles, 1), 512, GEMM_SMEM>>>(ah, lwh0, h1_ptr,
                                                   0, 1, Nn, b0);
    gemm_h<1><<<dim3(mtiles, 2), 512, GEMM_SMEM>>>(ah, wh0, hallh,
                                                   (size_t)Nn * D, NRELS / 2,
                                                   Nn, nullptr);
    scatter_kernel<<<scatterBlocks, 256>>>(h1_ptr, E, Nn);
    relu_half_kernel<<<(int)((nElem + 255) / 256), 256>>>(h1_ptr, ah, nElem);

    // ================= Layer 1 ==============================================
    glog_kernel<<<(Nn * 32 + 255) / 256, 256>>>(h1_ptr, gw1, Nn);
    gemm_h<0><<<dim3(mtiles, 1), 512, GEMM_SMEM>>>(ah, lwh1, out,
                                                   0, 1, Nn, b1);
    gemm_h<1><<<dim3(mtiles, 2), 512, GEMM_SMEM>>>(ah, wh1, hallh,
                                                   (size_t)Nn * D, NRELS / 2,
                                                   Nn, nullptr);
    scatter_kernel<<<scatterBlocks, 256>>>(out, E, Nn);
}